// round 7
// baseline (speedup 1.0000x reference)
#include <cuda_runtime.h>
#include <cuda_fp16.h>
#include <math.h>

#define NN 100000
#define EE 1600000
#define FD 128
#define HD 64

// Scratch (device globals)
__device__ int    g_cnt[2 * NN + 32];       // [0..NN)=out(src), [NN..2NN)=in(dst), [2NN]=ticket
__device__ float  g_nsrc[NN];
__device__ float  g_ndst[NN];
__device__ int    g_off[NN];
__device__ int    g_cursor[NN];
__device__ int    g_csr[EE];
__device__ __half g_x16[(size_t)NN * HD];   // x = feat@W1 (UNSCALED, fp16)
__device__ __half g_y16[(size_t)NN * HD];   // y = relu(agg1*ndst+b1)*nsrc (fp16)
__device__ float  g_a2[(size_t)NN * HD];    // agg2*ndst (fp32)

// ---------------------------------------------------------------------------
// Degrees: 1 edge/thread (max resident-atomic MLP, matches proven fill shape)
// ---------------------------------------------------------------------------
__global__ void deg_kernel(const int* __restrict__ src, const int* __restrict__ dst, int E) {
    int i = blockIdx.x * blockDim.x + threadIdx.x;
    if (i < E) {
        atomicAdd(&g_cnt[src[i]], 1);
        atomicAdd(&g_cnt[NN + dst[i]], 1);
    }
}

// ---------------------------------------------------------------------------
// Scan + norms fused (segments disjoint/unordered via atomic ticket)
// ---------------------------------------------------------------------------
__global__ void __launch_bounds__(256) scan_norm_kernel(int N) {
    __shared__ int wsum[8];
    __shared__ int sbase;
    int i = blockIdx.x * 256 + threadIdx.x;
    int lane = threadIdx.x & 31, wid = threadIdx.x >> 5;

    int cin = (i < N) ? g_cnt[NN + i] : 0;
    int x = cin;
#pragma unroll
    for (int o = 1; o < 32; o <<= 1) {
        int n = __shfl_up_sync(0xffffffffu, x, o);
        if (lane >= o) x += n;
    }
    if (lane == 31) wsum[wid] = x;
    __syncthreads();
    if (threadIdx.x == 0) {
        int run = 0;
#pragma unroll
        for (int w = 0; w < 8; w++) { run += wsum[w]; wsum[w] = run; }
        sbase = atomicAdd(&g_cnt[2 * NN], run);
    }
    __syncthreads();
    int excl = x - cin + (wid > 0 ? wsum[wid - 1] : 0) + sbase;
    if (i < N) {
        g_off[i] = excl;
        g_cursor[i] = excl;
        g_nsrc[i] = rsqrtf(fmaxf((float)g_cnt[i], 1.0f));
        g_ndst[i] = rsqrtf(fmaxf((float)cin, 1.0f));
    }
}

// ---------------------------------------------------------------------------
// Fill CSR: 1 edge per thread (R4-proven)
// ---------------------------------------------------------------------------
__global__ void fill_kernel(const int* __restrict__ src, const int* __restrict__ dst, int E) {
    int i = blockIdx.x * blockDim.x + threadIdx.x;
    if (i < E) {
        int p = atomicAdd(&g_cursor[dst[i]], 1);
        g_csr[p] = src[i];
    }
}

// ---------------------------------------------------------------------------
// GEMM1 (dependency-free): x16 = fp16( feat @ W1 )   [N,128]x[128,64]
// nsrc applied later, per-edge, in gather1.
// ---------------------------------------------------------------------------
__global__ void __launch_bounds__(256) gemm1_kernel(const float* __restrict__ feat,
                                                    const float* __restrict__ W1, int N) {
    __shared__ float As[64][68];
    __shared__ float Ws[64][64];
    int tx = threadIdx.x & 15, ty = threadIdx.x >> 4;
    int r0 = blockIdx.x * 64;

    float acc[4][4] = {};

    for (int k0 = 0; k0 < FD; k0 += 64) {
        for (int idx = threadIdx.x; idx < 1024; idx += 256) {
            int r = idx >> 4;
            int c4 = idx & 15;
            int row = r0 + r;
            float4 v = make_float4(0.f, 0.f, 0.f, 0.f);
            if (row < N) {
                v = *(const float4*)(feat + (size_t)row * FD + k0 + c4 * 4);
            }
            *(float4*)&As[r][c4 * 4] = v;
        }
        for (int idx = threadIdx.x; idx < 1024; idx += 256) {
            ((float4*)Ws)[idx] = ((const float4*)(W1 + (size_t)k0 * HD))[idx];
        }
        __syncthreads();

#pragma unroll
        for (int k = 0; k < 64; k++) {
            float a0 = As[ty * 4 + 0][k];
            float a1 = As[ty * 4 + 1][k];
            float a2 = As[ty * 4 + 2][k];
            float a3 = As[ty * 4 + 3][k];
            float4 w = *(float4*)&Ws[k][tx * 4];
            acc[0][0] += a0 * w.x; acc[0][1] += a0 * w.y; acc[0][2] += a0 * w.z; acc[0][3] += a0 * w.w;
            acc[1][0] += a1 * w.x; acc[1][1] += a1 * w.y; acc[1][2] += a1 * w.z; acc[1][3] += a1 * w.w;
            acc[2][0] += a2 * w.x; acc[2][1] += a2 * w.y; acc[2][2] += a2 * w.z; acc[2][3] += a2 * w.w;
            acc[3][0] += a3 * w.x; acc[3][1] += a3 * w.y; acc[3][2] += a3 * w.z; acc[3][3] += a3 * w.w;
        }
        __syncthreads();
    }

#pragma unroll
    for (int i = 0; i < 4; i++) {
        int row = r0 + ty * 4 + i;
        if (row < N) {
            __half2 h0 = __floats2half2_rn(acc[i][0], acc[i][1]);
            __half2 h1 = __floats2half2_rn(acc[i][2], acc[i][3]);
            uint2 pk;
            pk.x = *(unsigned*)&h0;
            pk.y = *(unsigned*)&h1;
            *(uint2*)(g_x16 + (size_t)row * HD + tx * 4) = pk;
        }
    }
}

// ---------------------------------------------------------------------------
// Gather 1 (scaled): sum_s x16[s]*nsrc[s]; then relu(*ndst+b1)*nsrc -> y16
// ---------------------------------------------------------------------------
__global__ void __launch_bounds__(256) gather1_kernel(const float* __restrict__ b1, int N) {
    int warp = (blockIdx.x * blockDim.x + threadIdx.x) >> 5;
    int lane = threadIdx.x & 31;
    if (warp >= N) return;
    int beg = g_off[warp];
    int end = beg + g_cnt[NN + warp];

    float ax = 0.f, ay = 0.f;
    int j = beg;
    for (; j + 32 <= end; j += 32) {
        int s = g_csr[j + lane];
#pragma unroll
        for (int t = 0; t < 32; t += 4) {
            int r0 = __shfl_sync(0xffffffffu, s, t + 0);
            int r1 = __shfl_sync(0xffffffffu, s, t + 1);
            int r2 = __shfl_sync(0xffffffffu, s, t + 2);
            int r3 = __shfl_sync(0xffffffffu, s, t + 3);
            float n0 = g_nsrc[r0], n1 = g_nsrc[r1], n2 = g_nsrc[r2], n3 = g_nsrc[r3];
            float2 v0 = __half22float2(*(const __half2*)(g_x16 + (size_t)r0 * HD + lane * 2));
            float2 v1 = __half22float2(*(const __half2*)(g_x16 + (size_t)r1 * HD + lane * 2));
            float2 v2 = __half22float2(*(const __half2*)(g_x16 + (size_t)r2 * HD + lane * 2));
            float2 v3 = __half22float2(*(const __half2*)(g_x16 + (size_t)r3 * HD + lane * 2));
            ax = fmaf(v0.x, n0, ax); ay = fmaf(v0.y, n0, ay);
            ax = fmaf(v1.x, n1, ax); ay = fmaf(v1.y, n1, ay);
            ax = fmaf(v2.x, n2, ax); ay = fmaf(v2.y, n2, ay);
            ax = fmaf(v3.x, n3, ax); ay = fmaf(v3.y, n3, ay);
        }
    }
    int rem = end - j;
    if (rem > 0) {
        int s = (lane < rem) ? g_csr[j + lane] : 0;
        int t = 0;
        for (; t + 4 <= rem; t += 4) {
            int r0 = __shfl_sync(0xffffffffu, s, t + 0);
            int r1 = __shfl_sync(0xffffffffu, s, t + 1);
            int r2 = __shfl_sync(0xffffffffu, s, t + 2);
            int r3 = __shfl_sync(0xffffffffu, s, t + 3);
            float n0 = g_nsrc[r0], n1 = g_nsrc[r1], n2 = g_nsrc[r2], n3 = g_nsrc[r3];
            float2 v0 = __half22float2(*(const __half2*)(g_x16 + (size_t)r0 * HD + lane * 2));
            float2 v1 = __half22float2(*(const __half2*)(g_x16 + (size_t)r1 * HD + lane * 2));
            float2 v2 = __half22float2(*(const __half2*)(g_x16 + (size_t)r2 * HD + lane * 2));
            float2 v3 = __half22float2(*(const __half2*)(g_x16 + (size_t)r3 * HD + lane * 2));
            ax = fmaf(v0.x, n0, ax); ay = fmaf(v0.y, n0, ay);
            ax = fmaf(v1.x, n1, ax); ay = fmaf(v1.y, n1, ay);
            ax = fmaf(v2.x, n2, ax); ay = fmaf(v2.y, n2, ay);
            ax = fmaf(v3.x, n3, ax); ay = fmaf(v3.y, n3, ay);
        }
        for (; t < rem; t++) {
            int r = __shfl_sync(0xffffffffu, s, t);
            float n = g_nsrc[r];
            float2 v = __half22float2(*(const __half2*)(g_x16 + (size_t)r * HD + lane * 2));
            ax = fmaf(v.x, n, ax); ay = fmaf(v.y, n, ay);
        }
    }

    float nd = g_ndst[warp];
    float ns = g_nsrc[warp];
    float2 b = *(const float2*)(b1 + lane * 2);
    float ox = fmaxf(ax * nd + b.x, 0.f) * ns;
    float oy = fmaxf(ay * nd + b.y, 0.f) * ns;
    *(__half2*)(g_y16 + (size_t)warp * HD + lane * 2) = __floats2half2_rn(ox, oy);
}

// ---------------------------------------------------------------------------
// Gather 2 (unscaled source; nsrc already folded into y16): a2 = (sum y16[s])*ndst
// ---------------------------------------------------------------------------
__global__ void __launch_bounds__(256) gather2_kernel(int N) {
    int warp = (blockIdx.x * blockDim.x + threadIdx.x) >> 5;
    int lane = threadIdx.x & 31;
    if (warp >= N) return;
    int beg = g_off[warp];
    int end = beg + g_cnt[NN + warp];

    float ax = 0.f, ay = 0.f;
    int j = beg;
    for (; j + 32 <= end; j += 32) {
        int s = g_csr[j + lane];
#pragma unroll
        for (int t = 0; t < 32; t += 4) {
            int r0 = __shfl_sync(0xffffffffu, s, t + 0);
            int r1 = __shfl_sync(0xffffffffu, s, t + 1);
            int r2 = __shfl_sync(0xffffffffu, s, t + 2);
            int r3 = __shfl_sync(0xffffffffu, s, t + 3);
            float2 v0 = __half22float2(*(const __half2*)(g_y16 + (size_t)r0 * HD + lane * 2));
            float2 v1 = __half22float2(*(const __half2*)(g_y16 + (size_t)r1 * HD + lane * 2));
            float2 v2 = __half22float2(*(const __half2*)(g_y16 + (size_t)r2 * HD + lane * 2));
            float2 v3 = __half22float2(*(const __half2*)(g_y16 + (size_t)r3 * HD + lane * 2));
            ax += (v0.x + v1.x) + (v2.x + v3.x);
            ay += (v0.y + v1.y) + (v2.y + v3.y);
        }
    }
    int rem = end - j;
    if (rem > 0) {
        int s = (lane < rem) ? g_csr[j + lane] : 0;
        int t = 0;
        for (; t + 4 <= rem; t += 4) {
            int r0 = __shfl_sync(0xffffffffu, s, t + 0);
            int r1 = __shfl_sync(0xffffffffu, s, t + 1);
            int r2 = __shfl_sync(0xffffffffu, s, t + 2);
            int r3 = __shfl_sync(0xffffffffu, s, t + 3);
            float2 v0 = __half22float2(*(const __half2*)(g_y16 + (size_t)r0 * HD + lane * 2));
            float2 v1 = __half22float2(*(const __half2*)(g_y16 + (size_t)r1 * HD + lane * 2));
            float2 v2 = __half22float2(*(const __half2*)(g_y16 + (size_t)r2 * HD + lane * 2));
            float2 v3 = __half22float2(*(const __half2*)(g_y16 + (size_t)r3 * HD + lane * 2));
            ax += (v0.x + v1.x) + (v2.x + v3.x);
            ay += (v0.y + v1.y) + (v2.y + v3.y);
        }
        for (; t < rem; t++) {
            int r = __shfl_sync(0xffffffffu, s, t);
            float2 v = __half22float2(*(const __half2*)(g_y16 + (size_t)r * HD + lane * 2));
            ax += v.x; ay += v.y;
        }
    }

    float nd = g_ndst[warp];
    *(float2*)(g_a2 + (size_t)warp * HD + lane * 2) = make_float2(ax * nd, ay * nd);
}

// ---------------------------------------------------------------------------
// Final: z = (a@W_mu + b_mu) + noise * exp(a@W_sig + b_sig), a = g_a2 — R4-proven
// ---------------------------------------------------------------------------
__global__ void __launch_bounds__(256) final_kernel(const float* __restrict__ noise,
                                                    const float* __restrict__ W_mu,
                                                    const float* __restrict__ b_mu,
                                                    const float* __restrict__ W_sig,
                                                    const float* __restrict__ b_sig,
                                                    float* __restrict__ out, int N) {
    __shared__ float As[64][36];
    __shared__ float Wc[32][128];
    int tx = threadIdx.x & 15, ty = threadIdx.x >> 4;
    int r0 = blockIdx.x * 64;

    float am[4][4] = {};
    float asg[4][4] = {};

    for (int k0 = 0; k0 < HD; k0 += 32) {
        for (int idx = threadIdx.x; idx < 512; idx += 256) {
            int r = idx >> 3;
            int c4 = idx & 7;
            int row = r0 + r;
            float4 v = make_float4(0.f, 0.f, 0.f, 0.f);
            if (row < N) v = *(const float4*)(g_a2 + (size_t)row * HD + k0 + c4 * 4);
            *(float4*)&As[r][c4 * 4] = v;
        }
        for (int idx = threadIdx.x; idx < 1024; idx += 256) {
            int k = idx >> 5;
            int c4 = idx & 31;
            if (c4 < 16) {
                *(float4*)&Wc[k][c4 * 4] = *(const float4*)(W_mu + (size_t)(k0 + k) * HD + c4 * 4);
            } else {
                *(float4*)&Wc[k][64 + (c4 - 16) * 4] =
                    *(const float4*)(W_sig + (size_t)(k0 + k) * HD + (c4 - 16) * 4);
            }
        }
        __syncthreads();

#pragma unroll
        for (int k = 0; k < 32; k++) {
            float a0 = As[ty * 4 + 0][k];
            float a1 = As[ty * 4 + 1][k];
            float a2 = As[ty * 4 + 2][k];
            float a3 = As[ty * 4 + 3][k];
            float4 wm = *(float4*)&Wc[k][tx * 4];
            float4 ws = *(float4*)&Wc[k][64 + tx * 4];
            am[0][0] += a0 * wm.x; am[0][1] += a0 * wm.y; am[0][2] += a0 * wm.z; am[0][3] += a0 * wm.w;
            am[1][0] += a1 * wm.x; am[1][1] += a1 * wm.y; am[1][2] += a1 * wm.z; am[1][3] += a1 * wm.w;
            am[2][0] += a2 * wm.x; am[2][1] += a2 * wm.y; am[2][2] += a2 * wm.z; am[2][3] += a2 * wm.w;
            am[3][0] += a3 * wm.x; am[3][1] += a3 * wm.y; am[3][2] += a3 * wm.z; am[3][3] += a3 * wm.w;
            asg[0][0] += a0 * ws.x; asg[0][1] += a0 * ws.y; asg[0][2] += a0 * ws.z; asg[0][3] += a0 * ws.w;
            asg[1][0] += a1 * ws.x; asg[1][1] += a1 * ws.y; asg[1][2] += a1 * ws.z; asg[1][3] += a1 * ws.w;
            asg[2][0] += a2 * ws.x; asg[2][1] += a2 * ws.y; asg[2][2] += a2 * ws.z; asg[2][3] += a2 * ws.w;
            asg[3][0] += a3 * ws.x; asg[3][1] += a3 * ws.y; asg[3][2] += a3 * ws.z; asg[3][3] += a3 * ws.w;
        }
        __syncthreads();
    }

    float4 bm = *(const float4*)(b_mu + tx * 4);
    float4 bs = *(const float4*)(b_sig + tx * 4);

#pragma unroll
    for (int i = 0; i < 4; i++) {
        int row = r0 + ty * 4 + i;
        if (row < N) {
            float4 nz = *(const float4*)(noise + (size_t)row * HD + tx * 4);
            float4 o;
            o.x = (am[i][0] + bm.x) + nz.x * expf(asg[i][0] + bs.x);
            o.y = (am[i][1] + bm.y) + nz.y * expf(asg[i][1] + bs.y);
            o.z = (am[i][2] + bm.z) + nz.z * expf(asg[i][2] + bs.z);
            o.w = (am[i][3] + bm.w) + nz.w * expf(asg[i][3] + bs.w);
            *(float4*)(out + (size_t)row * HD + tx * 4) = o;
        }
    }
}

// ---------------------------------------------------------------------------
// Launch: gemm1 has NO dependencies -> starts at t=0 on s2, fully hidden
// under the setup chain (memset -> deg -> scan -> fill) on the main stream.
// ---------------------------------------------------------------------------
static cudaStream_t s2 = nullptr;
static cudaEvent_t  evRoot = nullptr, evGemm = nullptr;

extern "C" void kernel_launch(void* const* d_in, const int* in_sizes, int n_in,
                              void* d_out, int out_size) {
    const float* feat  = (const float*)d_in[0];
    const int*   src   = (const int*)d_in[1];
    const int*   dst   = (const int*)d_in[2];
    const float* noise = (const float*)d_in[3];
    const float* W1    = (const float*)d_in[4];
    const float* b1    = (const float*)d_in[5];
    const float* W_mu  = (const float*)d_in[6];
    const float* b_mu  = (const float*)d_in[7];
    const float* W_sig = (const float*)d_in[8];
    const float* b_sig = (const float*)d_in[9];

    int N = in_sizes[0] / FD;
    int E = in_sizes[1];

    if (s2 == nullptr) {
        cudaStreamCreateWithFlags(&s2, cudaStreamNonBlocking);
        cudaEventCreateWithFlags(&evRoot, cudaEventDisableTiming);
        cudaEventCreateWithFlags(&evGemm, cudaEventDisableTiming);
    }

    void* p_cnt;
    cudaGetSymbolAddress(&p_cnt, g_cnt);

    // Fork: gemm1 immediately on s2 (no dependencies at all)
    cudaEventRecord(evRoot, 0);
    cudaStreamWaitEvent(s2, evRoot, 0);
    gemm1_kernel<<<(N + 63) / 64, 256, 0, s2>>>(feat, W1, N);
    cudaEventRecord(evGemm, s2);

    // Main stream: CSR build chain
    cudaMemsetAsync(p_cnt, 0, sizeof(int) * (2 * NN + 32));
    deg_kernel<<<(E + 255) / 256, 256>>>(src, dst, E);
    scan_norm_kernel<<<(N + 255) / 256, 256>>>(N);
    fill_kernel<<<(E + 255) / 256, 256>>>(src, dst, E);

    // Join: gather1 needs CSR + x16 + norms
    cudaStreamWaitEvent(0, evGemm, 0);

    int gblocks = (N * 32 + 255) / 256;
    gather1_kernel<<<gblocks, 256>>>(b1, N);
    gather2_kernel<<<gblocks, 256>>>(N);

    final_kernel<<<(N + 63) / 64, 256>>>(noise, W_mu, b_mu, W_sig, b_sig,
                                         (float*)d_out, N);
}

// round 8
// speedup vs baseline: 1.0234x; 1.0234x over previous
#include <cuda_runtime.h>
#include <cuda_fp16.h>
#include <math.h>

#define NN 100000
#define EE 1600000
#define FD 128
#define HD 64

// Scratch (device globals)
__device__ int    g_cnt[2 * NN + 32];       // [0..NN)=out, [NN..2NN)=in, [2NN]=scan ticket
__device__ float  g_nsrc[NN];
__device__ float  g_ndst[NN];
__device__ int    g_off[NN];
__device__ int    g_cursor[NN];
__device__ int    g_csr[EE];
__device__ __half g_x16[(size_t)NN * HD];   // x = (feat*nsrc)@W1 (fp16)
__device__ __half g_y16[(size_t)NN * HD];   // y = relu(agg1*ndst+b1)*nsrc (fp16)
__device__ float  g_a2[(size_t)NN * HD];    // agg2*ndst (fp32)

// ---------------------------------------------------------------------------
// Degrees (R4-proven: 4 edges/thread)
// ---------------------------------------------------------------------------
__global__ void deg_kernel(const int* __restrict__ src, const int* __restrict__ dst, int E) {
    int i = (blockIdx.x * blockDim.x + threadIdx.x) * 4;
    if (i + 4 <= E) {
        int4 s = *(const int4*)(src + i);
        int4 d = *(const int4*)(dst + i);
        atomicAdd(&g_cnt[s.x], 1); atomicAdd(&g_cnt[s.y], 1);
        atomicAdd(&g_cnt[s.z], 1); atomicAdd(&g_cnt[s.w], 1);
        atomicAdd(&g_cnt[NN + d.x], 1); atomicAdd(&g_cnt[NN + d.y], 1);
        atomicAdd(&g_cnt[NN + d.z], 1); atomicAdd(&g_cnt[NN + d.w], 1);
    } else {
        for (int j = i; j < E; j++) {
            atomicAdd(&g_cnt[src[j]], 1);
            atomicAdd(&g_cnt[NN + dst[j]], 1);
        }
    }
}

// ---------------------------------------------------------------------------
// Scan + norm fused (R4-proven)
// ---------------------------------------------------------------------------
__global__ void __launch_bounds__(256) scan_norm_kernel(int N) {
    __shared__ int wsum[8];
    __shared__ int sbase;
    int i = blockIdx.x * 256 + threadIdx.x;
    int lane = threadIdx.x & 31, wid = threadIdx.x >> 5;

    int cin = (i < N) ? g_cnt[NN + i] : 0;
    int x = cin;
#pragma unroll
    for (int o = 1; o < 32; o <<= 1) {
        int n = __shfl_up_sync(0xffffffffu, x, o);
        if (lane >= o) x += n;
    }
    if (lane == 31) wsum[wid] = x;
    __syncthreads();
    if (threadIdx.x == 0) {
        int run = 0;
#pragma unroll
        for (int w = 0; w < 8; w++) { run += wsum[w]; wsum[w] = run; }
        sbase = atomicAdd(&g_cnt[2 * NN], run);
    }
    __syncthreads();
    int excl = x - cin + (wid > 0 ? wsum[wid - 1] : 0) + sbase;
    if (i < N) {
        g_off[i] = excl;
        g_cursor[i] = excl;
        g_nsrc[i] = rsqrtf(fmaxf((float)g_cnt[i], 1.0f));
        g_ndst[i] = rsqrtf(fmaxf((float)cin, 1.0f));
    }
}

// ---------------------------------------------------------------------------
// Fill CSR: 1 edge per thread (R4-proven)
// ---------------------------------------------------------------------------
__global__ void fill_kernel(const int* __restrict__ src, const int* __restrict__ dst, int E) {
    int i = blockIdx.x * blockDim.x + threadIdx.x;
    if (i < E) {
        int p = atomicAdd(&g_cursor[dst[i]], 1);
        g_csr[p] = src[i];
    }
}

// ---------------------------------------------------------------------------
// GEMM1: x16 = fp16( (feat * nsrc) @ W1 )  (R4-proven)
// ---------------------------------------------------------------------------
__global__ void __launch_bounds__(256) gemm1_kernel(const float* __restrict__ feat,
                                                    const float* __restrict__ W1, int N) {
    __shared__ float As[64][68];
    __shared__ float Ws[64][64];
    int tx = threadIdx.x & 15, ty = threadIdx.x >> 4;
    int r0 = blockIdx.x * 64;

    float acc[4][4] = {};

    for (int k0 = 0; k0 < FD; k0 += 64) {
        for (int idx = threadIdx.x; idx < 1024; idx += 256) {
            int r = idx >> 4;
            int c4 = idx & 15;
            int row = r0 + r;
            float4 v = make_float4(0.f, 0.f, 0.f, 0.f);
            float s = 0.f;
            if (row < N) {
                v = *(const float4*)(feat + (size_t)row * FD + k0 + c4 * 4);
                s = g_nsrc[row];
            }
            v.x *= s; v.y *= s; v.z *= s; v.w *= s;
            *(float4*)&As[r][c4 * 4] = v;
        }
        for (int idx = threadIdx.x; idx < 1024; idx += 256) {
            ((float4*)Ws)[idx] = ((const float4*)(W1 + (size_t)k0 * HD))[idx];
        }
        __syncthreads();

#pragma unroll
        for (int k = 0; k < 64; k++) {
            float a0 = As[ty * 4 + 0][k];
            float a1 = As[ty * 4 + 1][k];
            float a2 = As[ty * 4 + 2][k];
            float a3 = As[ty * 4 + 3][k];
            float4 w = *(float4*)&Ws[k][tx * 4];
            acc[0][0] += a0 * w.x; acc[0][1] += a0 * w.y; acc[0][2] += a0 * w.z; acc[0][3] += a0 * w.w;
            acc[1][0] += a1 * w.x; acc[1][1] += a1 * w.y; acc[1][2] += a1 * w.z; acc[1][3] += a1 * w.w;
            acc[2][0] += a2 * w.x; acc[2][1] += a2 * w.y; acc[2][2] += a2 * w.z; acc[2][3] += a2 * w.w;
            acc[3][0] += a3 * w.x; acc[3][1] += a3 * w.y; acc[3][2] += a3 * w.z; acc[3][3] += a3 * w.w;
        }
        __syncthreads();
    }

#pragma unroll
    for (int i = 0; i < 4; i++) {
        int row = r0 + ty * 4 + i;
        if (row < N) {
            __half2 h0 = __floats2half2_rn(acc[i][0], acc[i][1]);
            __half2 h1 = __floats2half2_rn(acc[i][2], acc[i][3]);
            uint2 pk;
            pk.x = *(unsigned*)&h0;
            pk.y = *(unsigned*)&h1;
            *(uint2*)(g_x16 + (size_t)row * HD + tx * 4) = pk;
        }
    }
}

// ---------------------------------------------------------------------------
// Paired gather: 2 nodes per warp, 16 lanes per node, 8B (4 halves) per lane.
// One warp-wide load instruction serves one edge of EACH node -> 2 edges/inst.
// Half-warps are independent shuffle domains (masks 0xffff / 0xffff0000).
// ---------------------------------------------------------------------------
__device__ __forceinline__ void gather_half(const __half* __restrict__ X,
                                            int beg, int end, int sub, int base,
                                            unsigned hmask, float acc[4]) {
    acc[0] = 0.f; acc[1] = 0.f; acc[2] = 0.f; acc[3] = 0.f;
    int j = beg;
    for (; j + 16 <= end; j += 16) {
        int s = g_csr[j + sub];
#pragma unroll
        for (int t = 0; t < 16; t += 4) {
            int r0 = __shfl_sync(hmask, s, base + t + 0);
            int r1 = __shfl_sync(hmask, s, base + t + 1);
            int r2 = __shfl_sync(hmask, s, base + t + 2);
            int r3 = __shfl_sync(hmask, s, base + t + 3);
            uint2 p0 = *(const uint2*)(X + (size_t)r0 * HD + sub * 4);
            uint2 p1 = *(const uint2*)(X + (size_t)r1 * HD + sub * 4);
            uint2 p2 = *(const uint2*)(X + (size_t)r2 * HD + sub * 4);
            uint2 p3 = *(const uint2*)(X + (size_t)r3 * HD + sub * 4);
            float2 a, b;
            a = __half22float2(*(__half2*)&p0.x); b = __half22float2(*(__half2*)&p0.y);
            acc[0] += a.x; acc[1] += a.y; acc[2] += b.x; acc[3] += b.y;
            a = __half22float2(*(__half2*)&p1.x); b = __half22float2(*(__half2*)&p1.y);
            acc[0] += a.x; acc[1] += a.y; acc[2] += b.x; acc[3] += b.y;
            a = __half22float2(*(__half2*)&p2.x); b = __half22float2(*(__half2*)&p2.y);
            acc[0] += a.x; acc[1] += a.y; acc[2] += b.x; acc[3] += b.y;
            a = __half22float2(*(__half2*)&p3.x); b = __half22float2(*(__half2*)&p3.y);
            acc[0] += a.x; acc[1] += a.y; acc[2] += b.x; acc[3] += b.y;
        }
    }
    int rem = end - j;
    if (rem > 0) {
        int s = (sub < rem) ? g_csr[j + sub] : 0;
        for (int t = 0; t < rem; t++) {
            int r = __shfl_sync(hmask, s, base + t);
            uint2 p = *(const uint2*)(X + (size_t)r * HD + sub * 4);
            float2 a = __half22float2(*(__half2*)&p.x);
            float2 b = __half22float2(*(__half2*)&p.y);
            acc[0] += a.x; acc[1] += a.y; acc[2] += b.x; acc[3] += b.y;
        }
    }
}

__global__ void __launch_bounds__(256) gather1_kernel(const float* __restrict__ b1, int N) {
    int warp = (blockIdx.x * blockDim.x + threadIdx.x) >> 5;
    int lane = threadIdx.x & 31;
    int half = lane >> 4;
    int sub  = lane & 15;
    int node = warp * 2 + half;
    if (node >= N) return;
    unsigned hmask = half ? 0xffff0000u : 0x0000ffffu;
    int base = half << 4;

    int beg = g_off[node];
    int end = beg + g_cnt[NN + node];

    float acc[4];
    gather_half(g_x16, beg, end, sub, base, hmask, acc);

    float nd = g_ndst[node];
    float ns = g_nsrc[node];
    float4 b = *(const float4*)(b1 + sub * 4);
    float o0 = fmaxf(acc[0] * nd + b.x, 0.f) * ns;
    float o1 = fmaxf(acc[1] * nd + b.y, 0.f) * ns;
    float o2 = fmaxf(acc[2] * nd + b.z, 0.f) * ns;
    float o3 = fmaxf(acc[3] * nd + b.w, 0.f) * ns;
    __half2 h0 = __floats2half2_rn(o0, o1);
    __half2 h1 = __floats2half2_rn(o2, o3);
    uint2 pk;
    pk.x = *(unsigned*)&h0;
    pk.y = *(unsigned*)&h1;
    *(uint2*)(g_y16 + (size_t)node * HD + sub * 4) = pk;
}

__global__ void __launch_bounds__(256) gather2_kernel(int N) {
    int warp = (blockIdx.x * blockDim.x + threadIdx.x) >> 5;
    int lane = threadIdx.x & 31;
    int half = lane >> 4;
    int sub  = lane & 15;
    int node = warp * 2 + half;
    if (node >= N) return;
    unsigned hmask = half ? 0xffff0000u : 0x0000ffffu;
    int base = half << 4;

    int beg = g_off[node];
    int end = beg + g_cnt[NN + node];

    float acc[4];
    gather_half(g_y16, beg, end, sub, base, hmask, acc);

    float nd = g_ndst[node];
    float4 o = make_float4(acc[0] * nd, acc[1] * nd, acc[2] * nd, acc[3] * nd);
    *(float4*)(g_a2 + (size_t)node * HD + sub * 4) = o;
}

// ---------------------------------------------------------------------------
// Final: z = (a@W_mu + b_mu) + noise * exp(a@W_sig + b_sig), a = g_a2 (R4-proven)
// ---------------------------------------------------------------------------
__global__ void __launch_bounds__(256) final_kernel(const float* __restrict__ noise,
                                                    const float* __restrict__ W_mu,
                                                    const float* __restrict__ b_mu,
                                                    const float* __restrict__ W_sig,
                                                    const float* __restrict__ b_sig,
                                                    float* __restrict__ out, int N) {
    __shared__ float As[64][36];
    __shared__ float Wc[32][128];
    int tx = threadIdx.x & 15, ty = threadIdx.x >> 4;
    int r0 = blockIdx.x * 64;

    float am[4][4] = {};
    float asg[4][4] = {};

    for (int k0 = 0; k0 < HD; k0 += 32) {
        for (int idx = threadIdx.x; idx < 512; idx += 256) {
            int r = idx >> 3;
            int c4 = idx & 7;
            int row = r0 + r;
            float4 v = make_float4(0.f, 0.f, 0.f, 0.f);
            if (row < N) v = *(const float4*)(g_a2 + (size_t)row * HD + k0 + c4 * 4);
            *(float4*)&As[r][c4 * 4] = v;
        }
        for (int idx = threadIdx.x; idx < 1024; idx += 256) {
            int k = idx >> 5;
            int c4 = idx & 31;
            if (c4 < 16) {
                *(float4*)&Wc[k][c4 * 4] = *(const float4*)(W_mu + (size_t)(k0 + k) * HD + c4 * 4);
            } else {
                *(float4*)&Wc[k][64 + (c4 - 16) * 4] =
                    *(const float4*)(W_sig + (size_t)(k0 + k) * HD + (c4 - 16) * 4);
            }
        }
        __syncthreads();

#pragma unroll
        for (int k = 0; k < 32; k++) {
            float a0 = As[ty * 4 + 0][k];
            float a1 = As[ty * 4 + 1][k];
            float a2 = As[ty * 4 + 2][k];
            float a3 = As[ty * 4 + 3][k];
            float4 wm = *(float4*)&Wc[k][tx * 4];
            float4 ws = *(float4*)&Wc[k][64 + tx * 4];
            am[0][0] += a0 * wm.x; am[0][1] += a0 * wm.y; am[0][2] += a0 * wm.z; am[0][3] += a0 * wm.w;
            am[1][0] += a1 * wm.x; am[1][1] += a1 * wm.y; am[1][2] += a1 * wm.z; am[1][3] += a1 * wm.w;
            am[2][0] += a2 * wm.x; am[2][1] += a2 * wm.y; am[2][2] += a2 * wm.z; am[2][3] += a2 * wm.w;
            am[3][0] += a3 * wm.x; am[3][1] += a3 * wm.y; am[3][2] += a3 * wm.z; am[3][3] += a3 * wm.w;
            asg[0][0] += a0 * ws.x; asg[0][1] += a0 * ws.y; asg[0][2] += a0 * ws.z; asg[0][3] += a0 * ws.w;
            asg[1][0] += a1 * ws.x; asg[1][1] += a1 * ws.y; asg[1][2] += a1 * ws.z; asg[1][3] += a1 * ws.w;
            asg[2][0] += a2 * ws.x; asg[2][1] += a2 * ws.y; asg[2][2] += a2 * ws.z; asg[2][3] += a2 * ws.w;
            asg[3][0] += a3 * ws.x; asg[3][1] += a3 * ws.y; asg[3][2] += a3 * ws.z; asg[3][3] += a3 * ws.w;
        }
        __syncthreads();
    }

    float4 bm = *(const float4*)(b_mu + tx * 4);
    float4 bs = *(const float4*)(b_sig + tx * 4);

#pragma unroll
    for (int i = 0; i < 4; i++) {
        int row = r0 + ty * 4 + i;
        if (row < N) {
            float4 nz = *(const float4*)(noise + (size_t)row * HD + tx * 4);
            float4 o;
            o.x = (am[i][0] + bm.x) + nz.x * expf(asg[i][0] + bs.x);
            o.y = (am[i][1] + bm.y) + nz.y * expf(asg[i][1] + bs.y);
            o.z = (am[i][2] + bm.z) + nz.z * expf(asg[i][2] + bs.z);
            o.w = (am[i][3] + bm.w) + nz.w * expf(asg[i][3] + bs.w);
            *(float4*)(out + (size_t)row * HD + tx * 4) = o;
        }
    }
}

// ---------------------------------------------------------------------------
// Launch — exact R4 structure
// ---------------------------------------------------------------------------
static cudaStream_t s2 = nullptr;
static cudaEvent_t  evScan = nullptr, evGemm = nullptr;

extern "C" void kernel_launch(void* const* d_in, const int* in_sizes, int n_in,
                              void* d_out, int out_size) {
    const float* feat  = (const float*)d_in[0];
    const int*   src   = (const int*)d_in[1];
    const int*   dst   = (const int*)d_in[2];
    const float* noise = (const float*)d_in[3];
    const float* W1    = (const float*)d_in[4];
    const float* b1    = (const float*)d_in[5];
    const float* W_mu  = (const float*)d_in[6];
    const float* b_mu  = (const float*)d_in[7];
    const float* W_sig = (const float*)d_in[8];
    const float* b_sig = (const float*)d_in[9];

    int N = in_sizes[0] / FD;
    int E = in_sizes[1];

    if (s2 == nullptr) {
        cudaStreamCreateWithFlags(&s2, cudaStreamNonBlocking);
        cudaEventCreateWithFlags(&evScan, cudaEventDisableTiming);
        cudaEventCreateWithFlags(&evGemm, cudaEventDisableTiming);
    }

    void* p_cnt;
    cudaGetSymbolAddress(&p_cnt, g_cnt);
    cudaMemsetAsync(p_cnt, 0, sizeof(int) * (2 * NN + 32));

    deg_kernel<<<(E / 4 + 255) / 256, 256>>>(src, dst, E);
    scan_norm_kernel<<<(N + 255) / 256, 256>>>(N);
    cudaEventRecord(evScan, 0);

    // gemm1 (needs nsrc only) overlaps with fill on stream 2
    cudaStreamWaitEvent(s2, evScan, 0);
    gemm1_kernel<<<(N + 63) / 64, 256, 0, s2>>>(feat, W1, N);
    cudaEventRecord(evGemm, s2);

    fill_kernel<<<(E + 255) / 256, 256>>>(src, dst, E);
    cudaStreamWaitEvent(0, evGemm, 0);

    // Paired gathers: 2 nodes per warp
    int nwarps = (N + 1) / 2;
    int gblocks = (nwarps * 32 + 255) / 256;
    gather1_kernel<<<gblocks, 256>>>(b1, N);
    gather2_kernel<<<gblocks, 256>>>(N);

    final_kernel<<<(N + 63) / 64, 256>>>(noise, W_mu, b_mu, W_sig, b_sig,
                                         (float*)d_out, N);
}

// round 9
// speedup vs baseline: 1.2883x; 1.2588x over previous
#include <cuda_runtime.h>
#include <cuda_fp16.h>
#include <mma.h>
#include <math.h>

using namespace nvcuda;

#define NN 100000
#define EE 1600000
#define FD 128
#define HD 64

// Scratch (device globals)
__device__ int    g_cnt[2 * NN + 32];       // [0..NN)=out, [NN..2NN)=in, [2NN]=scan ticket
__device__ float  g_nsrc[NN];
__device__ float  g_ndst[NN];
__device__ int    g_off[NN];
__device__ int    g_cursor[NN];
__device__ int    g_csr[EE];
__device__ __half g_x16[(size_t)NN * HD];   // x = (feat*nsrc)@W1 (fp16)
__device__ __half g_y16[(size_t)NN * HD];   // y = relu(agg1*ndst+b1)*nsrc (fp16)
__device__ __half g_a16[(size_t)NN * HD];   // agg2*ndst (fp16, wmma A input)

// ---------------------------------------------------------------------------
// Degrees (R4-proven: 4 edges/thread)
// ---------------------------------------------------------------------------
__global__ void deg_kernel(const int* __restrict__ src, const int* __restrict__ dst, int E) {
    int i = (blockIdx.x * blockDim.x + threadIdx.x) * 4;
    if (i + 4 <= E) {
        int4 s = *(const int4*)(src + i);
        int4 d = *(const int4*)(dst + i);
        atomicAdd(&g_cnt[s.x], 1); atomicAdd(&g_cnt[s.y], 1);
        atomicAdd(&g_cnt[s.z], 1); atomicAdd(&g_cnt[s.w], 1);
        atomicAdd(&g_cnt[NN + d.x], 1); atomicAdd(&g_cnt[NN + d.y], 1);
        atomicAdd(&g_cnt[NN + d.z], 1); atomicAdd(&g_cnt[NN + d.w], 1);
    } else {
        for (int j = i; j < E; j++) {
            atomicAdd(&g_cnt[src[j]], 1);
            atomicAdd(&g_cnt[NN + dst[j]], 1);
        }
    }
}

// ---------------------------------------------------------------------------
// Scan + norm fused (R4-proven)
// ---------------------------------------------------------------------------
__global__ void __launch_bounds__(256) scan_norm_kernel(int N) {
    __shared__ int wsum[8];
    __shared__ int sbase;
    int i = blockIdx.x * 256 + threadIdx.x;
    int lane = threadIdx.x & 31, wid = threadIdx.x >> 5;

    int cin = (i < N) ? g_cnt[NN + i] : 0;
    int x = cin;
#pragma unroll
    for (int o = 1; o < 32; o <<= 1) {
        int n = __shfl_up_sync(0xffffffffu, x, o);
        if (lane >= o) x += n;
    }
    if (lane == 31) wsum[wid] = x;
    __syncthreads();
    if (threadIdx.x == 0) {
        int run = 0;
#pragma unroll
        for (int w = 0; w < 8; w++) { run += wsum[w]; wsum[w] = run; }
        sbase = atomicAdd(&g_cnt[2 * NN], run);
    }
    __syncthreads();
    int excl = x - cin + (wid > 0 ? wsum[wid - 1] : 0) + sbase;
    if (i < N) {
        g_off[i] = excl;
        g_cursor[i] = excl;
        g_nsrc[i] = rsqrtf(fmaxf((float)g_cnt[i], 1.0f));
        g_ndst[i] = rsqrtf(fmaxf((float)cin, 1.0f));
    }
}

// ---------------------------------------------------------------------------
// Fill CSR: 1 edge per thread (R4-proven)
// ---------------------------------------------------------------------------
__global__ void fill_kernel(const int* __restrict__ src, const int* __restrict__ dst, int E) {
    int i = blockIdx.x * blockDim.x + threadIdx.x;
    if (i < E) {
        int p = atomicAdd(&g_cursor[dst[i]], 1);
        g_csr[p] = src[i];
    }
}

// ---------------------------------------------------------------------------
// GEMM1 (wmma HMMA): x16 = fp16( (feat * nsrc) @ W1 ), fp32 accumulate
// Tile: 64 rows x 64 cols, K=128 in one smem pass. 8 warps, 2 frags/warp.
// ---------------------------------------------------------------------------
__global__ void __launch_bounds__(256) gemm1_kernel(const float* __restrict__ feat,
                                                    const float* __restrict__ W1, int N) {
    __shared__ __align__(32) __half As[64][136];   // 17408 B (pad: conflict-free ldmatrix)
    __shared__ __align__(32) __half Bs[128][72];   // 18432 B
    int tid = threadIdx.x;
    int w = tid >> 5;
    int r0 = blockIdx.x * 64;

    // A: 64 rows x 128 k (fp32 -> fp16 with nsrc scale). 2048 float4.
    for (int idx = tid; idx < 2048; idx += 256) {
        int r = idx >> 5;          // 32 float4 per row
        int c4 = idx & 31;
        int row = r0 + r;
        float4 v = make_float4(0.f, 0.f, 0.f, 0.f);
        float s = 0.f;
        if (row < N) {
            v = ((const float4*)(feat + (size_t)row * FD))[c4];
            s = g_nsrc[row];
        }
        __half2 h0 = __floats2half2_rn(v.x * s, v.y * s);
        __half2 h1 = __floats2half2_rn(v.z * s, v.w * s);
        uint2 pk; pk.x = *(unsigned*)&h0; pk.y = *(unsigned*)&h1;
        *(uint2*)&As[r][c4 * 4] = pk;
    }
    // B: W1 [128 x 64] fp32 -> fp16. 2048 float4.
    for (int idx = tid; idx < 2048; idx += 256) {
        int k = idx >> 4;          // 16 float4 per row
        int c4 = idx & 15;
        float4 v = ((const float4*)(W1 + (size_t)k * HD))[c4];
        __half2 h0 = __floats2half2_rn(v.x, v.y);
        __half2 h1 = __floats2half2_rn(v.z, v.w);
        uint2 pk; pk.x = *(unsigned*)&h0; pk.y = *(unsigned*)&h1;
        *(uint2*)&Bs[k][c4 * 4] = pk;
    }
    __syncthreads();

    int rg = w >> 1;               // row group (16 rows)
    int cg = (w & 1) * 2;          // first of two 16-col groups
    wmma::fragment<wmma::accumulator, 16, 16, 16, float> c0, c1;
    wmma::fill_fragment(c0, 0.0f);
    wmma::fill_fragment(c1, 0.0f);
#pragma unroll
    for (int k = 0; k < 8; k++) {
        wmma::fragment<wmma::matrix_a, 16, 16, 16, __half, wmma::row_major> a;
        wmma::fragment<wmma::matrix_b, 16, 16, 16, __half, wmma::row_major> b0, b1;
        wmma::load_matrix_sync(a, &As[rg * 16][k * 16], 136);
        wmma::load_matrix_sync(b0, &Bs[k * 16][cg * 16], 72);
        wmma::load_matrix_sync(b1, &Bs[k * 16][(cg + 1) * 16], 72);
        wmma::mma_sync(c0, a, b0, c0);
        wmma::mma_sync(c1, a, b1, c1);
    }
    __syncthreads();

    float* Cs = (float*)&As[0][0];     // 64 x 68 fp32 = 17408 B (exactly As)
    wmma::store_matrix_sync(Cs + (rg * 16) * 68 + cg * 16, c0, 68, wmma::mem_row_major);
    wmma::store_matrix_sync(Cs + (rg * 16) * 68 + (cg + 1) * 16, c1, 68, wmma::mem_row_major);
    __syncthreads();

    for (int idx = tid; idx < 1024; idx += 256) {   // 64 rows x 16 uint2
        int r = idx >> 4;
        int c4 = idx & 15;
        int row = r0 + r;
        if (row < N) {
            const float* p = Cs + r * 68 + c4 * 4;
            __half2 h0 = __floats2half2_rn(p[0], p[1]);
            __half2 h1 = __floats2half2_rn(p[2], p[3]);
            uint2 pk; pk.x = *(unsigned*)&h0; pk.y = *(unsigned*)&h1;
            *(uint2*)(g_x16 + (size_t)row * HD + c4 * 4) = pk;
        }
    }
}

// ---------------------------------------------------------------------------
// Shuffle-batched gather core (~1 LDG per edge) — R4-proven
// ---------------------------------------------------------------------------
__device__ __forceinline__ void gather_row(const __half* __restrict__ X,
                                           int beg, int end, int lane,
                                           float& ax, float& ay) {
    ax = 0.f; ay = 0.f;
    int j = beg;
    for (; j + 32 <= end; j += 32) {
        int s = g_csr[j + lane];
#pragma unroll
        for (int t = 0; t < 32; t += 4) {
            int r0 = __shfl_sync(0xffffffffu, s, t + 0);
            int r1 = __shfl_sync(0xffffffffu, s, t + 1);
            int r2 = __shfl_sync(0xffffffffu, s, t + 2);
            int r3 = __shfl_sync(0xffffffffu, s, t + 3);
            float2 v0 = __half22float2(*(const __half2*)(X + (size_t)r0 * HD + lane * 2));
            float2 v1 = __half22float2(*(const __half2*)(X + (size_t)r1 * HD + lane * 2));
            float2 v2 = __half22float2(*(const __half2*)(X + (size_t)r2 * HD + lane * 2));
            float2 v3 = __half22float2(*(const __half2*)(X + (size_t)r3 * HD + lane * 2));
            ax += (v0.x + v1.x) + (v2.x + v3.x);
            ay += (v0.y + v1.y) + (v2.y + v3.y);
        }
    }
    int rem = end - j;
    if (rem > 0) {
        int s = (lane < rem) ? g_csr[j + lane] : 0;
        int t = 0;
        for (; t + 4 <= rem; t += 4) {
            int r0 = __shfl_sync(0xffffffffu, s, t + 0);
            int r1 = __shfl_sync(0xffffffffu, s, t + 1);
            int r2 = __shfl_sync(0xffffffffu, s, t + 2);
            int r3 = __shfl_sync(0xffffffffu, s, t + 3);
            float2 v0 = __half22float2(*(const __half2*)(X + (size_t)r0 * HD + lane * 2));
            float2 v1 = __half22float2(*(const __half2*)(X + (size_t)r1 * HD + lane * 2));
            float2 v2 = __half22float2(*(const __half2*)(X + (size_t)r2 * HD + lane * 2));
            float2 v3 = __half22float2(*(const __half2*)(X + (size_t)r3 * HD + lane * 2));
            ax += (v0.x + v1.x) + (v2.x + v3.x);
            ay += (v0.y + v1.y) + (v2.y + v3.y);
        }
        for (; t < rem; t++) {
            int r = __shfl_sync(0xffffffffu, s, t);
            float2 v = __half22float2(*(const __half2*)(X + (size_t)r * HD + lane * 2));
            ax += v.x; ay += v.y;
        }
    }
}

__global__ void __launch_bounds__(256) gather1_kernel(const float* __restrict__ b1, int N) {
    int warp = (blockIdx.x * blockDim.x + threadIdx.x) >> 5;
    int lane = threadIdx.x & 31;
    if (warp >= N) return;
    int beg = g_off[warp];
    int end = beg + g_cnt[NN + warp];

    float ax, ay;
    gather_row(g_x16, beg, end, lane, ax, ay);

    float nd = g_ndst[warp];
    float ns = g_nsrc[warp];
    float2 b = *(const float2*)(b1 + lane * 2);
    float ox = fmaxf(ax * nd + b.x, 0.f) * ns;
    float oy = fmaxf(ay * nd + b.y, 0.f) * ns;
    *(__half2*)(g_y16 + (size_t)warp * HD + lane * 2) = __floats2half2_rn(ox, oy);
}

__global__ void __launch_bounds__(256) gather2_kernel(int N) {
    int warp = (blockIdx.x * blockDim.x + threadIdx.x) >> 5;
    int lane = threadIdx.x & 31;
    if (warp >= N) return;
    int beg = g_off[warp];
    int end = beg + g_cnt[NN + warp];

    float ax, ay;
    gather_row(g_y16, beg, end, lane, ax, ay);

    float nd = g_ndst[warp];
    *(__half2*)(g_a16 + (size_t)warp * HD + lane * 2) = __floats2half2_rn(ax * nd, ay * nd);
}

// ---------------------------------------------------------------------------
// Final (wmma HMMA dual-GEMM): C = a16 @ [W_mu | W_sig], fp32 accumulate;
// epilogue z = (mu + b_mu) + noise * exp(ls + b_sig).
// Tile 64 rows x 128 cols, K=64. 8 warps x 4 fragments.
// ---------------------------------------------------------------------------
__global__ void __launch_bounds__(256) final_kernel(const float* __restrict__ noise,
                                                    const float* __restrict__ W_mu,
                                                    const float* __restrict__ b_mu,
                                                    const float* __restrict__ W_sig,
                                                    const float* __restrict__ b_sig,
                                                    float* __restrict__ out, int N) {
    __shared__ __align__(32) char sbuf[64 * 132 * 4];    // 33792 B union
    __half* As = (__half*)sbuf;                          // [64][72]  = 9216 B
    __half* Bs = (__half*)(sbuf + 9216);                 // [64][136] = 17408 B
    float*  Cs = (float*)sbuf;                           // [64][132] (after mma)
    int tid = threadIdx.x;
    int w = tid >> 5;
    int r0 = blockIdx.x * 64;

    // A: g_a16 rows (fp16), 64 x 16 uint2
    for (int idx = tid; idx < 1024; idx += 256) {
        int r = idx >> 4;
        int c4 = idx & 15;
        int row = r0 + r;
        uint2 pk = make_uint2(0u, 0u);
        if (row < N) pk = *(const uint2*)(g_a16 + (size_t)row * HD + c4 * 4);
        *(uint2*)&As[r * 72 + c4 * 4] = pk;
    }
    // B: [W_mu | W_sig] -> fp16, 64 rows x 128 cols. 2048 float4.
    for (int idx = tid; idx < 2048; idx += 256) {
        int k = idx >> 5;          // 32 float4 per Bs row
        int c4 = idx & 31;
        float4 v = (c4 < 16) ? ((const float4*)(W_mu + (size_t)k * HD))[c4]
                             : ((const float4*)(W_sig + (size_t)k * HD))[c4 - 16];
        __half2 h0 = __floats2half2_rn(v.x, v.y);
        __half2 h1 = __floats2half2_rn(v.z, v.w);
        uint2 pk; pk.x = *(unsigned*)&h0; pk.y = *(unsigned*)&h1;
        *(uint2*)&Bs[k * 136 + c4 * 4] = pk;
    }
    __syncthreads();

    int rg = w >> 1;               // row group (16 rows)
    int ch = (w & 1) * 4;          // 4 col fragments (64 cols)
    wmma::fragment<wmma::accumulator, 16, 16, 16, float> c[4];
#pragma unroll
    for (int f = 0; f < 4; f++) wmma::fill_fragment(c[f], 0.0f);
#pragma unroll
    for (int k = 0; k < 4; k++) {
        wmma::fragment<wmma::matrix_a, 16, 16, 16, __half, wmma::row_major> a;
        wmma::load_matrix_sync(a, &As[rg * 16 * 72 + k * 16], 72);
#pragma unroll
        for (int f = 0; f < 4; f++) {
            wmma::fragment<wmma::matrix_b, 16, 16, 16, __half, wmma::row_major> b;
            wmma::load_matrix_sync(b, &Bs[k * 16 * 136 + (ch + f) * 16], 136);
            wmma::mma_sync(c[f], a, b, c[f]);
        }
    }
    __syncthreads();
#pragma unroll
    for (int f = 0; f < 4; f++)
        wmma::store_matrix_sync(Cs + (rg * 16) * 132 + (ch + f) * 16, c[f], 132,
                                wmma::mem_row_major);
    __syncthreads();

    // Epilogue: 64 rows x 64 outputs
    int tx = tid & 15, ty = tid >> 4;
    float4 bm = *(const float4*)(b_mu + tx * 4);
    float4 bsg = *(const float4*)(b_sig + tx * 4);
#pragma unroll
    for (int i = 0; i < 4; i++) {
        int r = ty * 4 + i;
        int row = r0 + r;
        if (row < N) {
            const float* pm = Cs + r * 132 + tx * 4;
            const float* ps = Cs + r * 132 + 64 + tx * 4;
            float4 nz = *(const float4*)(noise + (size_t)row * HD + tx * 4);
            float4 o;
            o.x = (pm[0] + bm.x) + nz.x * expf(ps[0] + bsg.x);
            o.y = (pm[1] + bm.y) + nz.y * expf(ps[1] + bsg.y);
            o.z = (pm[2] + bm.z) + nz.z * expf(ps[2] + bsg.z);
            o.w = (pm[3] + bm.w) + nz.w * expf(ps[3] + bsg.w);
            *(float4*)(out + (size_t)row * HD + tx * 4) = o;
        }
    }
}

// ---------------------------------------------------------------------------
// Launch — exact R4 structure
// ---------------------------------------------------------------------------
static cudaStream_t s2 = nullptr;
static cudaEvent_t  evScan = nullptr, evGemm = nullptr;

extern "C" void kernel_launch(void* const* d_in, const int* in_sizes, int n_in,
                              void* d_out, int out_size) {
    const float* feat  = (const float*)d_in[0];
    const int*   src   = (const int*)d_in[1];
    const int*   dst   = (const int*)d_in[2];
    const float* noise = (const float*)d_in[3];
    const float* W1    = (const float*)d_in[4];
    const float* b1    = (const float*)d_in[5];
    const float* W_mu  = (const float*)d_in[6];
    const float* b_mu  = (const float*)d_in[7];
    const float* W_sig = (const float*)d_in[8];
    const float* b_sig = (const float*)d_in[9];

    int N = in_sizes[0] / FD;
    int E = in_sizes[1];

    if (s2 == nullptr) {
        cudaStreamCreateWithFlags(&s2, cudaStreamNonBlocking);
        cudaEventCreateWithFlags(&evScan, cudaEventDisableTiming);
        cudaEventCreateWithFlags(&evGemm, cudaEventDisableTiming);
    }

    void* p_cnt;
    cudaGetSymbolAddress(&p_cnt, g_cnt);
    cudaMemsetAsync(p_cnt, 0, sizeof(int) * (2 * NN + 32));

    deg_kernel<<<(E / 4 + 255) / 256, 256>>>(src, dst, E);
    scan_norm_kernel<<<(N + 255) / 256, 256>>>(N);
    cudaEventRecord(evScan, 0);

    // gemm1 (needs nsrc only) overlaps with fill on stream 2
    cudaStreamWaitEvent(s2, evScan, 0);
    gemm1_kernel<<<(N + 63) / 64, 256, 0, s2>>>(feat, W1, N);
    cudaEventRecord(evGemm, s2);

    fill_kernel<<<(E + 255) / 256, 256>>>(src, dst, E);
    cudaStreamWaitEvent(0, evGemm, 0);

    int gblocks = (N * 32 + 255) / 256;
    gather1_kernel<<<gblocks, 256>>>(b1, N);
    gather2_kernel<<<gblocks, 256>>>(N);

    final_kernel<<<(N + 63) / 64, 256>>>(noise, W_mu, b_mu, W_sig, b_sig,
                                         (float*)d_out, N);
}